// round 6
// baseline (speedup 1.0000x reference)
#include <cuda_runtime.h>

// Problem shape
#define B    4
#define T    8192
#define D    512
#define CH   8                 // time steps per chunk (per block)
#define NC   (T / CH)          // 1024 chunks per sequence
#define TPB  128               // threads; each owns 4 channels
#define LBW  4                 // lookback window

// Flag states
#define FLG_NONE 0
#define FLG_AGG  1
#define FLG_PREF 2

// Scratch (device globals; zero-initialized at module load).
__device__ float2 g_aggv [B * NC * D];       // per-chunk (a = prod f, h = local end)
__device__ float  g_prefh[B * NC * D];       // per-chunk inclusive-prefix h
__device__ int    g_flag [B * NC * TPB];     // per-(chunk, thread-quad) state

__device__ __forceinline__ float tanha(float x) {
    float y;
    asm("tanh.approx.f32 %0, %1;" : "=f"(y) : "f"(x));
    return y;
}
__device__ __forceinline__ float sigm(float x) {
    return fmaf(tanha(0.5f * x), 0.5f, 0.5f);
}

__global__ void __launch_bounds__(TPB, 10)
scan_onepass(const float* __restrict__ x, float* __restrict__ out) {
    const int c   = blockIdx.x;           // chunk (predecessors have lower bid)
    const int b   = blockIdx.y;           // batch
    const int tid = threadIdx.x;
    const int d   = tid * 4;

    const float* base  = x   + ((size_t)b * T + (size_t)c * CH) * (3 * D);
    float*       obase = out + ((size_t)b * T + (size_t)c * CH) * D;

    // ---------------- Phase 1: local chunk scan (no stash) ----------------
    float a0 = 1.f, a1 = 1.f, a2 = 1.f, a3 = 1.f;
    float h0 = 0.f, h1 = 0.f, h2 = 0.f, h3 = 0.f;

#pragma unroll
    for (int t = 0; t < CH; ++t) {
        const float4 vi = *(const float4*)(base + (size_t)t * (3 * D) + d);
        const float4 gi = *(const float4*)(base + (size_t)t * (3 * D) + D + d);

        float i0 = sigm(gi.x), i1 = sigm(gi.y), i2 = sigm(gi.z), i3 = sigm(gi.w);
        float f0 = 1.f - i0,   f1 = 1.f - i1,   f2 = 1.f - i2,   f3 = 1.f - i3;
        float w0 = i0 * tanha(vi.x), w1 = i1 * tanha(vi.y);
        float w2 = i2 * tanha(vi.z), w3 = i3 * tanha(vi.w);

        a0 *= f0; a1 *= f1; a2 *= f2; a3 *= f3;
        h0 = fmaf(f0, h0, w0);
        h1 = fmaf(f1, h1, w1);
        h2 = fmaf(f2, h2, w2);
        h3 = fmaf(f3, h3, w3);
    }

    const size_t sidx  = ((size_t)b * NC + c) * D + d;
    const int    fbase = (b * NC) * TPB + tid;

    float He0 = 0.f, He1 = 0.f, He2 = 0.f, He3 = 0.f;  // exclusive prefix h

    if (c == 0) {
        __stcg(&g_prefh[sidx + 0], h0);
        __stcg(&g_prefh[sidx + 1], h1);
        __stcg(&g_prefh[sidx + 2], h2);
        __stcg(&g_prefh[sidx + 3], h3);
        __threadfence();
        *(volatile int*)&g_flag[fbase + 0 * TPB] = FLG_PREF;
    } else {
        __stcg((float2*)&g_aggv[sidx + 0], make_float2(a0, h0));
        __stcg((float2*)&g_aggv[sidx + 1], make_float2(a1, h1));
        __stcg((float2*)&g_aggv[sidx + 2], make_float2(a2, h2));
        __stcg((float2*)&g_aggv[sidx + 3], make_float2(a3, h3));
        __threadfence();
        *(volatile int*)&g_flag[fbase + c * TPB] = FLG_AGG;

        // ---------------- Phase 2: decoupled lookback ----------------------
        float As0 = 1.f, As1 = 1.f, As2 = 1.f, As3 = 1.f;
        float Bs0 = 0.f, Bs1 = 0.f, Bs2 = 0.f, Bs3 = 0.f;

        int p = c - 1;
        bool done = false;
        while (!done) {
            const int w = (p + 1 < LBW) ? (p + 1) : LBW;

            int fl[LBW];
            for (;;) {
                bool all = true;
#pragma unroll
                for (int k = 0; k < LBW; ++k) {
                    if (k < w) {
                        fl[k] = *(volatile int*)&g_flag[fbase + (p - k) * TPB];
                        all &= (fl[k] != FLG_NONE);
                    }
                }
                if (all) break;
            }
            __threadfence();

            int kpref = -1;
#pragma unroll
            for (int k = 0; k < LBW; ++k)
                if (k < w && kpref < 0 && fl[k] == FLG_PREF) kpref = k;
            const int kend = (kpref >= 0) ? kpref : (w - 1);

            for (int k = 0; k <= kend; ++k) {
                const size_t vb = ((size_t)b * NC + (p - k)) * D + d;
                if (k == kpref) {
                    float p0 = __ldcg(&g_prefh[vb + 0]);
                    float p1 = __ldcg(&g_prefh[vb + 1]);
                    float p2 = __ldcg(&g_prefh[vb + 2]);
                    float p3 = __ldcg(&g_prefh[vb + 3]);
                    He0 = fmaf(As0, p0, Bs0);
                    He1 = fmaf(As1, p1, Bs1);
                    He2 = fmaf(As2, p2, Bs2);
                    He3 = fmaf(As3, p3, Bs3);
                    done = true;
                    break;
                } else {
                    float2 q0 = __ldcg(&g_aggv[vb + 0]);
                    float2 q1 = __ldcg(&g_aggv[vb + 1]);
                    float2 q2 = __ldcg(&g_aggv[vb + 2]);
                    float2 q3 = __ldcg(&g_aggv[vb + 3]);
                    Bs0 = fmaf(As0, q0.y, Bs0); As0 *= q0.x;
                    Bs1 = fmaf(As1, q1.y, Bs1); As1 *= q1.x;
                    Bs2 = fmaf(As2, q2.y, Bs2); As2 *= q2.x;
                    Bs3 = fmaf(As3, q3.y, Bs3); As3 *= q3.x;
                }
            }
            if (!done) {
                p -= w;
                if (p < 0) {
                    He0 = Bs0; He1 = Bs1; He2 = Bs2; He3 = Bs3;
                    done = true;
                }
            }
        }

        __stcg(&g_prefh[sidx + 0], fmaf(a0, He0, h0));
        __stcg(&g_prefh[sidx + 1], fmaf(a1, He1, h1));
        __stcg(&g_prefh[sidx + 2], fmaf(a2, He2, h2));
        __stcg(&g_prefh[sidx + 3], fmaf(a3, He3, h3));
        __threadfence();
        *(volatile int*)&g_flag[fbase + c * TPB] = FLG_PREF;
    }

    // ---------- Phase 3: recompute from L2-resident vi/gi, emit -----------
    float k0 = He0, k1 = He1, k2 = He2, k3 = He3;
#pragma unroll
    for (int t = 0; t < CH; ++t) {
        const float4 vi = *(const float4*)(base + (size_t)t * (3 * D) + d);
        const float4 gi = *(const float4*)(base + (size_t)t * (3 * D) + D + d);
        const float4 go = *(const float4*)(base + (size_t)t * (3 * D) + 2 * D + d);

        float i0 = sigm(gi.x), i1 = sigm(gi.y), i2 = sigm(gi.z), i3 = sigm(gi.w);
        float f0 = 1.f - i0,   f1 = 1.f - i1,   f2 = 1.f - i2,   f3 = 1.f - i3;
        float w0 = i0 * tanha(vi.x), w1 = i1 * tanha(vi.y);
        float w2 = i2 * tanha(vi.z), w3 = i3 * tanha(vi.w);

        k0 = fmaf(f0, k0, w0);
        k1 = fmaf(f1, k1, w1);
        k2 = fmaf(f2, k2, w2);
        k3 = fmaf(f3, k3, w3);

        float4 o4;
        o4.x = tanha(k0) * sigm(go.x);
        o4.y = tanha(k1) * sigm(go.y);
        o4.z = tanha(k2) * sigm(go.z);
        o4.w = tanha(k3) * sigm(go.w);
        *(float4*)(obase + (size_t)t * D + d) = o4;
    }
}

extern "C" void kernel_launch(void* const* d_in, const int* in_sizes, int n_in,
                              void* d_out, int out_size) {
    const float* x = (const float*)d_in[0];
    float* out = (float*)d_out;

    dim3 grid(NC, B);   // 1024 x 4 = 4096 blocks; blockIdx.x = chunk (bid-ordered)
    scan_onepass<<<grid, TPB>>>(x, out);
}

// round 7
// speedup vs baseline: 1.4641x; 1.4641x over previous
#include <cuda_runtime.h>

// Problem shape
#define B    4
#define T    8192
#define D    512
#define CH   8                 // time steps per chunk (per block)
#define NC   (T / CH)          // 1024 chunks per sequence
#define TPB  128               // threads per block
#define NDG  2                 // D-groups (channel halves) per chunk
#define DG   (D / NDG)         // 256 channels per block
#define LBW  4                 // lookback window

// Flag states
#define FLG_NONE 0
#define FLG_AGG  1
#define FLG_PREF 2

// Scratch (device globals; zero-initialized at module load).
__device__ float2 g_aggv [B * NC * D];            // per-chunk (a, h_local_end)
__device__ float  g_prefh[B * NC * D];            // per-chunk inclusive-prefix h
__device__ int    g_flag [B * NDG * NC * TPB];    // per-(b, dgroup, chunk, thread)

__device__ __forceinline__ float tanha(float x) {
    float y;
    asm("tanh.approx.f32 %0, %1;" : "=f"(y) : "f"(x));
    return y;
}
__device__ __forceinline__ float sigm(float x) {
    return fmaf(tanha(0.5f * x), 0.5f, 0.5f);
}
__device__ __forceinline__ void st_release(int* p, int v) {
    asm volatile("st.release.gpu.global.b32 [%0], %1;" :: "l"(p), "r"(v) : "memory");
}
__device__ __forceinline__ int ld_acquire(const int* p) {
    int v;
    asm volatile("ld.acquire.gpu.global.b32 %0, [%1];" : "=r"(v) : "l"(p) : "memory");
    return v;
}

__global__ void __launch_bounds__(TPB, 12)
scan_onepass(const float* __restrict__ x, float* __restrict__ out) {
    // Per-thread-private stash (no cross-thread sharing, no __syncthreads).
    __shared__ float2 sm_f [CH * TPB];   // (f0, f1) per (t, thread)
    __shared__ float2 sm_iv[CH * TPB];   // (iv0, iv1)

    const int c   = blockIdx.x;          // chunk (predecessors have lower bid)
    const int dg  = blockIdx.y;          // channel half
    const int b   = blockIdx.z;          // batch
    const int tid = threadIdx.x;
    const int ch  = dg * DG + tid * 2;   // absolute channel base (owns 2)

    const float* base  = x   + ((size_t)b * T + (size_t)c * CH) * (3 * D) + ch;
    float*       obase = out + ((size_t)b * T + (size_t)c * CH) * D + ch;

    // ---------------- Phase 1: local chunk scan, stash f and i*v ----------
    float a0 = 1.f, a1 = 1.f;
    float h0 = 0.f, h1 = 0.f;

#pragma unroll
    for (int t = 0; t < CH; ++t) {
        const float2 vi = __ldcs((const float2*)(base + (size_t)t * (3 * D)));
        const float2 gi = __ldcs((const float2*)(base + (size_t)t * (3 * D) + D));

        float i0 = sigm(gi.x), i1 = sigm(gi.y);
        float f0 = 1.f - i0,   f1 = 1.f - i1;
        float w0 = i0 * tanha(vi.x), w1 = i1 * tanha(vi.y);

        sm_f [t * TPB + tid] = make_float2(f0, f1);
        sm_iv[t * TPB + tid] = make_float2(w0, w1);

        a0 *= f0; a1 *= f1;
        h0 = fmaf(f0, h0, w0);
        h1 = fmaf(f1, h1, w1);
    }

    const size_t sidx  = ((size_t)b * NC + c) * D + ch;      // value index (2 ch)
    const int    fbase = ((b * NDG + dg) * NC) * TPB + tid;  // flag index helper

    float He0 = 0.f, He1 = 0.f;          // exclusive prefix h

    if (c == 0) {
        __stcg((float2*)&g_prefh[sidx], make_float2(h0, h1));
        st_release(&g_flag[fbase + 0 * TPB], FLG_PREF);
    } else {
        __stcg((float4*)&g_aggv[sidx], make_float4(a0, h0, a1, h1));
        st_release(&g_flag[fbase + c * TPB], FLG_AGG);

        // ---------------- Phase 2: decoupled lookback ----------------------
        float As0 = 1.f, As1 = 1.f;
        float Bs0 = 0.f, Bs1 = 0.f;

        int p = c - 1;
        bool done = false;
        while (!done) {
            const int w = (p + 1 < LBW) ? (p + 1) : LBW;

            int fl[LBW];
            for (;;) {
                bool all = true;
#pragma unroll
                for (int k = 0; k < LBW; ++k) {
                    if (k < w) {
                        fl[k] = ld_acquire(&g_flag[fbase + (p - k) * TPB]);
                        all &= (fl[k] != FLG_NONE);
                    }
                }
                if (all) break;
            }

            int kpref = -1;
#pragma unroll
            for (int k = 0; k < LBW; ++k)
                if (k < w && kpref < 0 && fl[k] == FLG_PREF) kpref = k;
            const int kend = (kpref >= 0) ? kpref : (w - 1);

            for (int k = 0; k <= kend; ++k) {
                const size_t vb = ((size_t)b * NC + (p - k)) * D + ch;
                if (k == kpref) {
                    float2 pv = __ldcg((const float2*)&g_prefh[vb]);
                    He0 = fmaf(As0, pv.x, Bs0);
                    He1 = fmaf(As1, pv.y, Bs1);
                    done = true;
                    break;
                } else {
                    float4 q = __ldcg((const float4*)&g_aggv[vb]);
                    Bs0 = fmaf(As0, q.y, Bs0); As0 *= q.x;
                    Bs1 = fmaf(As1, q.w, Bs1); As1 *= q.z;
                }
            }
            if (!done) {
                p -= w;
                if (p < 0) {
                    He0 = Bs0; He1 = Bs1;
                    done = true;
                }
            }
        }

        __stcg((float2*)&g_prefh[sidx],
               make_float2(fmaf(a0, He0, h0), fmaf(a1, He1, h1)));
        st_release(&g_flag[fbase + c * TPB], FLG_PREF);
    }

    // ---------------- Phase 3: replay from smem stash, emit ----------------
    float k0 = He0, k1 = He1;
#pragma unroll
    for (int t = 0; t < CH; ++t) {
        const float2 go = __ldcs((const float2*)(base + (size_t)t * (3 * D) + 2 * D));
        const float2 ff = sm_f [t * TPB + tid];
        const float2 iv = sm_iv[t * TPB + tid];

        k0 = fmaf(ff.x, k0, iv.x);
        k1 = fmaf(ff.y, k1, iv.y);

        float2 o2;
        o2.x = tanha(k0) * sigm(go.x);
        o2.y = tanha(k1) * sigm(go.y);
        __stcs((float2*)(obase + (size_t)t * D), o2);
    }
}

extern "C" void kernel_launch(void* const* d_in, const int* in_sizes, int n_in,
                              void* d_out, int out_size) {
    const float* x = (const float*)d_in[0];
    float* out = (float*)d_out;

    dim3 grid(NC, NDG, B);   // 1024 x 2 x 4 = 8192 blocks
    scan_onepass<<<grid, TPB>>>(x, out);
}

// round 8
// speedup vs baseline: 1.7257x; 1.1787x over previous
#include <cuda_runtime.h>

// Problem shape
#define B    4
#define T    8192
#define D    512
#define CH   8                 // time steps per chunk (per block)
#define NC   (T / CH)          // 1024 chunks per sequence
#define TPB  128               // threads per block
#define NDG  2                 // D-groups (channel halves) per chunk
#define DG   (D / NDG)         // 256 channels per block
#define LBW  4                 // lookback window

// Flag states
#define FLG_NONE 0
#define FLG_AGG  1
#define FLG_PREF 2

// Scratch (device globals; zero-initialized at module load).
__device__ float2 g_aggv [B * NC * D];            // per-chunk (a, h_local_end)
__device__ float  g_prefh[B * NC * D];            // per-chunk inclusive-prefix h
__device__ int    g_flag [B * NDG * NC * TPB];    // per-(b, dgroup, chunk, thread)

__device__ __forceinline__ float tanha(float x) {
    float y;
    asm("tanh.approx.f32 %0, %1;" : "=f"(y) : "f"(x));
    return y;
}
__device__ __forceinline__ float sigm(float x) {
    return fmaf(tanha(0.5f * x), 0.5f, 0.5f);
}
__device__ __forceinline__ void st_release(int* p, int v) {
    asm volatile("st.release.gpu.global.b32 [%0], %1;" :: "l"(p), "r"(v) : "memory");
}
__device__ __forceinline__ int ld_acquire(const int* p) {
    int v;
    asm volatile("ld.acquire.gpu.global.b32 %0, [%1];" : "=r"(v) : "l"(p) : "memory");
    return v;
}

__global__ void __launch_bounds__(TPB, 8)
scan_onepass(const float* __restrict__ x, float* __restrict__ out) {
    // Per-thread-private stash (no cross-thread sharing, no __syncthreads).
    __shared__ float2 sm_f [CH * TPB];   // (f0, f1) per (t, thread)
    __shared__ float2 sm_iv[CH * TPB];   // (iv0, iv1)

    const int c   = blockIdx.x;          // chunk (predecessors have lower bid)
    const int dg  = blockIdx.y;          // channel half
    const int b   = blockIdx.z;          // batch
    const int tid = threadIdx.x;
    const int ch  = dg * DG + tid * 2;   // absolute channel base (owns 2)

    const float* base  = x   + ((size_t)b * T + (size_t)c * CH) * (3 * D) + ch;
    float*       obase = out + ((size_t)b * T + (size_t)c * CH) * D + ch;

    // ---------------- Phase 1a: batch ALL input loads first (max MLP) ------
    float2 V[CH], G[CH];
#pragma unroll
    for (int t = 0; t < CH; ++t) {
        V[t] = __ldcs((const float2*)(base + (size_t)t * (3 * D)));
        G[t] = __ldcs((const float2*)(base + (size_t)t * (3 * D) + D));
    }

    // ---------------- Phase 1b: local chunk scan, stash f and i*v ----------
    float a0 = 1.f, a1 = 1.f;
    float h0 = 0.f, h1 = 0.f;
#pragma unroll
    for (int t = 0; t < CH; ++t) {
        float i0 = sigm(G[t].x), i1 = sigm(G[t].y);
        float f0 = 1.f - i0,     f1 = 1.f - i1;
        float w0 = i0 * tanha(V[t].x), w1 = i1 * tanha(V[t].y);

        sm_f [t * TPB + tid] = make_float2(f0, f1);
        sm_iv[t * TPB + tid] = make_float2(w0, w1);

        a0 *= f0; a1 *= f1;
        h0 = fmaf(f0, h0, w0);
        h1 = fmaf(f1, h1, w1);
    }

    // Prefetch the output-gate stream NOW so it overlaps the lookback chain.
    float2 GO[CH];
#pragma unroll
    for (int t = 0; t < CH; ++t)
        GO[t] = __ldcs((const float2*)(base + (size_t)t * (3 * D) + 2 * D));

    const size_t sidx  = ((size_t)b * NC + c) * D + ch;      // value index (2 ch)
    const int    fbase = ((b * NDG + dg) * NC) * TPB + tid;  // flag index helper

    float He0 = 0.f, He1 = 0.f;          // exclusive prefix h

    if (c == 0) {
        __stcg((float2*)&g_prefh[sidx], make_float2(h0, h1));
        st_release(&g_flag[fbase + 0 * TPB], FLG_PREF);
    } else {
        __stcg((float4*)&g_aggv[sidx], make_float4(a0, h0, a1, h1));
        st_release(&g_flag[fbase + c * TPB], FLG_AGG);

        // ---------------- Phase 2: decoupled lookback ----------------------
        float As0 = 1.f, As1 = 1.f;
        float Bs0 = 0.f, Bs1 = 0.f;

        int p = c - 1;
        bool done = false;
        while (!done) {
            const int w = (p + 1 < LBW) ? (p + 1) : LBW;

            int fl[LBW];
            for (;;) {
                bool all = true;
#pragma unroll
                for (int k = 0; k < LBW; ++k) {
                    if (k < w) {
                        fl[k] = ld_acquire(&g_flag[fbase + (p - k) * TPB]);
                        all &= (fl[k] != FLG_NONE);
                    }
                }
                if (all) break;
            }

            int kpref = -1;
#pragma unroll
            for (int k = 0; k < LBW; ++k)
                if (k < w && kpref < 0 && fl[k] == FLG_PREF) kpref = k;
            const int kend = (kpref >= 0) ? kpref : (w - 1);

            for (int k = 0; k <= kend; ++k) {
                const size_t vb = ((size_t)b * NC + (p - k)) * D + ch;
                if (k == kpref) {
                    float2 pv = __ldcg((const float2*)&g_prefh[vb]);
                    He0 = fmaf(As0, pv.x, Bs0);
                    He1 = fmaf(As1, pv.y, Bs1);
                    done = true;
                    break;
                } else {
                    float4 q = __ldcg((const float4*)&g_aggv[vb]);
                    Bs0 = fmaf(As0, q.y, Bs0); As0 *= q.x;
                    Bs1 = fmaf(As1, q.w, Bs1); As1 *= q.z;
                }
            }
            if (!done) {
                p -= w;
                if (p < 0) {
                    He0 = Bs0; He1 = Bs1;
                    done = true;
                }
            }
        }

        __stcg((float2*)&g_prefh[sidx],
               make_float2(fmaf(a0, He0, h0), fmaf(a1, He1, h1)));
        st_release(&g_flag[fbase + c * TPB], FLG_PREF);
    }

    // ---------------- Phase 3: replay from smem stash, emit ----------------
    float k0 = He0, k1 = He1;
#pragma unroll
    for (int t = 0; t < CH; ++t) {
        const float2 ff = sm_f [t * TPB + tid];
        const float2 iv = sm_iv[t * TPB + tid];

        k0 = fmaf(ff.x, k0, iv.x);
        k1 = fmaf(ff.y, k1, iv.y);

        float2 o2;
        o2.x = tanha(k0) * sigm(GO[t].x);
        o2.y = tanha(k1) * sigm(GO[t].y);
        __stcs((float2*)(obase + (size_t)t * D), o2);
    }
}

extern "C" void kernel_launch(void* const* d_in, const int* in_sizes, int n_in,
                              void* d_out, int out_size) {
    const float* x = (const float*)d_in[0];
    float* out = (float*)d_out;

    dim3 grid(NC, NDG, B);   // 1024 x 2 x 4 = 8192 blocks
    scan_onepass<<<grid, TPB>>>(x, out);
}